// round 3
// baseline (speedup 1.0000x reference)
#include <cuda_runtime.h>
#include <cuda_bf16.h>
#include <math.h>

// Problem constants
#define BT   256
#define TT   250
#define II   700
#define HH   128
#define OO   20
#define B_J0 0.01f
#define BETA 1.8f

// Output layout (flattened tuple): output[256*20], s1[256*128], s2[256*128], A_norm[1]
#define OUT_OFF_ACC  0
#define OUT_OFF_S1   (BT*OO)              // 5120
#define OUT_OFF_S2   (OUT_OFF_S1 + BT*HH) // 37888
#define OUT_OFF_NORM (OUT_OFF_S2 + BT*HH) // 70656

// Scratch for xin[T][B][H] (32 MB) — static device array (no allocations allowed)
__device__ float g_xin[TT * BT * HH];

// ---------------------------------------------------------------------------
// Kernel 1: xin = einsum('bti,ih->tbh', x, w_ih1) + b_ih1
// Classic 128x128x8 SGEMM, single accumulator per element, strictly
// increasing k with FMA (matches cuBLAS SGEMM / Eigen gebp accumulation).
// ---------------------------------------------------------------------------
__global__ __launch_bounds__(256) void gemm_xin_kernel(
    const float* __restrict__ x,      // [B,T,I] row stride 700
    const float* __restrict__ w,      // [I,H]
    const float* __restrict__ bias,   // [H]
    float* __restrict__ xin)          // [T,B,H]
{
    __shared__ float As[8][128];  // [k][m]
    __shared__ float Bs[8][128];  // [k][n]

    const int tid = threadIdx.x;
    const int tx = tid & 15;      // n subtile (8 wide)
    const int ty = tid >> 4;      // m subtile (8 tall)
    const int bm = blockIdx.x * 128;

    float acc[8][8];
#pragma unroll
    for (int i = 0; i < 8; i++)
#pragma unroll
        for (int j = 0; j < 8; j++) acc[i][j] = 0.f;

    const int la_m = tid >> 1;          // 0..127
    const int la_k = (tid & 1) * 4;     // 0 or 4
    const int lb_k = tid >> 5;          // 0..7
    const int lb_n = (tid & 31) * 4;    // 0..124

    const float* xA = x + (size_t)(bm + la_m) * II + la_k;

    for (int k0 = 0; k0 < II; k0 += 8) {
        float4 av;
        if (k0 + la_k + 3 < II) av = *(const float4*)(xA + k0);
        else                    av = make_float4(0.f, 0.f, 0.f, 0.f);
        As[la_k + 0][la_m] = av.x;
        As[la_k + 1][la_m] = av.y;
        As[la_k + 2][la_m] = av.z;
        As[la_k + 3][la_m] = av.w;

        float4 bv;
        int kk = k0 + lb_k;
        if (kk < II) bv = *(const float4*)(w + (size_t)kk * HH + lb_n);
        else         bv = make_float4(0.f, 0.f, 0.f, 0.f);
        *(float4*)&Bs[lb_k][lb_n] = bv;

        __syncthreads();

#pragma unroll
        for (int k = 0; k < 8; k++) {
            float a8[8], b8[8];
            *(float4*)(a8)     = *(const float4*)&As[k][ty * 8];
            *(float4*)(a8 + 4) = *(const float4*)&As[k][ty * 8 + 4];
            *(float4*)(b8)     = *(const float4*)&Bs[k][tx * 8];
            *(float4*)(b8 + 4) = *(const float4*)&Bs[k][tx * 8 + 4];
#pragma unroll
            for (int i = 0; i < 8; i++)
#pragma unroll
                for (int j = 0; j < 8; j++)
                    acc[i][j] = fmaf(a8[i], b8[j], acc[i][j]);
        }
        __syncthreads();
    }

    // epilogue: row m = b*250 + t -> write to xin[(t*256 + b)*128 + n], add bias
    float bn[8];
#pragma unroll
    for (int j = 0; j < 8; j++) bn[j] = bias[tx * 8 + j];

#pragma unroll
    for (int im = 0; im < 8; im++) {
        int mg = bm + ty * 8 + im;
        int bb = mg / TT;
        int tt = mg - bb * TT;
        float* op = xin + ((size_t)tt * BT + bb) * HH + tx * 8;
        float4 v0, v1;
        v0.x = __fadd_rn(acc[im][0], bn[0]);
        v0.y = __fadd_rn(acc[im][1], bn[1]);
        v0.z = __fadd_rn(acc[im][2], bn[2]);
        v0.w = __fadd_rn(acc[im][3], bn[3]);
        v1.x = __fadd_rn(acc[im][4], bn[4]);
        v1.y = __fadd_rn(acc[im][5], bn[5]);
        v1.z = __fadd_rn(acc[im][6], bn[6]);
        v1.w = __fadd_rn(acc[im][7], bn[7]);
        *(float4*)(op)     = v0;
        *(float4*)(op + 4) = v1;
    }
}

// ---------------------------------------------------------------------------
// Sparse dot: SINGLE accumulator, strictly increasing index order, pure adds.
// Bit-identical to a dense sequential FMA k-loop over {0,1} spikes.
// ---------------------------------------------------------------------------
__device__ __forceinline__ float sparse_dot128(const float* __restrict__ wsm,
                                               const int* __restrict__ lst,
                                               int cnt, int h)
{
    float q = 0.f;
#pragma unroll 4
    for (int i = 0; i < cnt; i++) q = __fadd_rn(q, wsm[(lst[i] << 7) + h]);
    return q;
}

__device__ __forceinline__ float sparse_dot20(const float* __restrict__ wsm,
                                              const int* __restrict__ lst,
                                              int cnt, int o)
{
    float q = 0.f;
#pragma unroll 4
    for (int i = 0; i < cnt; i++) q = __fadd_rn(q, wsm[lst[i] * OO + o]);
    return q;
}

// exp(-1/tau) computed in double then rounded: correctly-rounded fp32 exp,
// agrees with both glibc expf and CUDA expf for these arguments.
__device__ __forceinline__ float decay(float tau)
{
    float u = __fdiv_rn(-1.0f, tau);
    return (float)exp((double)u);
}

// ---------------------------------------------------------------------------
// Kernel 2: the scan. 128 CTAs x 256 threads; CTA c owns batch rows 2c, 2c+1.
// All elementwise math uses non-contracted __fmul_rn/__fadd_rn/__fsub_rn in
// the reference's exact association order (XLA does NOT fuse mul+add).
// ---------------------------------------------------------------------------
#define SCAN_SMEM_BYTES ((16384*3 + 2560)*4 + 256*4*2 + 16*4)

__global__ __launch_bounds__(256, 1) void scan_kernel(
    const float* __restrict__ xin,        // [T,B,H]
    const float* __restrict__ mask,       // [2,H,H]
    const float* __restrict__ w_h1h1, const float* __restrict__ b_h1h1,
    const float* __restrict__ w_h1h2, const float* __restrict__ b_h1h2,
    const float* __restrict__ w_h2h2, const float* __restrict__ b_h2h2,
    const float* __restrict__ w_h2o,  const float* __restrict__ b_h2o,
    const float* __restrict__ tau_adp_h1, const float* __restrict__ tau_adp_h2,
    const float* __restrict__ tau_m_h1,   const float* __restrict__ tau_m_h2,
    const float* __restrict__ tau_m_o,
    const float* __restrict__ hid1_mem0,  const float* __restrict__ hid2_mem0,
    const float* __restrict__ out_mem0,
    float* __restrict__ out)
{
    extern __shared__ unsigned char smraw[];
    float* w11s = (float*)smraw;          // 16384  (masked)
    float* w12s = w11s + 16384;           // 16384
    float* w22s = w12s + 16384;           // 16384  (masked)
    float* w2os = w22s + 16384;           // 2560
    int*   list1 = (int*)(w2os + 2560);   // [2][128]
    int*   list2 = list1 + 256;           // [2][128]
    unsigned* m1s = (unsigned*)(list2 + 256); // [8]
    unsigned* m2s = m1s + 8;                  // [8]

    const int tid  = threadIdx.x;
    const int r    = tid >> 7;
    const int h    = tid & 127;
    const int wid  = tid >> 5;
    const int lane = tid & 31;
    const int grow = blockIdx.x * 2 + r;

    // ---- load weights into smem (apply dropout mask to recurrent mats) ----
    for (int i = tid; i < 16384; i += 256) {
        w11s[i] = __fmul_rn(w_h1h1[i], mask[i]);
        w12s[i] = w_h1h2[i];
        w22s[i] = __fmul_rn(w_h2h2[i], mask[16384 + i]);
    }
    for (int i = tid; i < 2560; i += 256) w2os[i] = w_h2o[i];
    if (tid < 8) { m1s[tid] = 0u; m2s[tid] = 0u; }

    // ---- per-thread parameters & state ----
    const float a1 = decay(tau_m_h1[h]);
    const float r1 = decay(tau_adp_h1[h]);
    const float a2 = decay(tau_m_h2[h]);
    const float r2 = decay(tau_adp_h2[h]);
    const float oma1 = __fsub_rn(1.0f, a1);
    const float omr1 = __fsub_rn(1.0f, r1);
    const float oma2 = __fsub_rn(1.0f, a2);
    const float omr2 = __fsub_rn(1.0f, r2);
    const float b11r = b_h1h1[h];
    const float b12a = b_h1h2[h];
    const float b12b = b_h2h2[h];

    float h1m = hid1_mem0[grow * HH + h];
    float h2m = hid2_mem0[grow * HH + h];
    float b1 = B_J0, b2 = B_J0;
    float h1sp = 0.f, h2sp = 0.f;
    float s1c = 0.f, s2c = 0.f;
    int c1 = 0, c2 = 0;

    // readout state: warp 0 handles row 0, warp 5 handles row 1
    const bool ro = (wid == 0) || (wid == 5);
    float om = 0.f, aoo = 0.f, omao = 0.f, bo = 0.f, acc = 0.f;
    if (ro && lane < OO) {
        om   = out_mem0[grow * OO + lane];
        aoo  = decay(tau_m_o[lane]);
        omao = __fsub_rn(1.0f, aoo);
        bo   = b_h2o[lane];
    }
    __syncthreads();

    float xt = xin[((size_t)0 * BT + grow) * HH + h];

    for (int t = 0; t < TT; t++) {
        float xnext = (t + 1 < TT) ? __ldg(&xin[((size_t)(t + 1) * BT + grow) * HH + h]) : 0.f;

        // ---- layer 1 ----  i1 = (xt + h1s@w11) + b   (reference add order)
        float d11 = sparse_dot128(w11s, list1 + (r << 7), c1, h);
        float i1 = __fadd_rn(__fadd_rn(xt, d11), b11r);
        b1 = __fadd_rn(__fmul_rn(r1, b1), __fmul_rn(omr1, h1sp));
        float B1 = __fadd_rn(B_J0, __fmul_rn(BETA, b1));
        h1m = __fsub_rn(__fadd_rn(__fmul_rn(h1m, a1), __fmul_rn(oma1, i1)),
                        __fmul_rn(B1, h1sp));
        float sp1 = (__fsub_rn(h1m, B1) > 0.0f) ? 1.0f : 0.0f;
        s1c += sp1;

        unsigned bal1 = __ballot_sync(0xffffffffu, sp1 != 0.0f);
        if (lane == 0) m1s[wid] = bal1;
        __syncthreads();

        unsigned n10 = m1s[r * 4 + 0], n11 = m1s[r * 4 + 1];
        unsigned n12 = m1s[r * 4 + 2], n13 = m1s[r * 4 + 3];
        {
            int w4 = wid & 3;
            int off = 0;
            if (w4 > 0) off += __popc(n10);
            if (w4 > 1) off += __popc(n11);
            if (w4 > 2) off += __popc(n12);
            if (sp1 != 0.0f) {
                int pos = off + __popc(bal1 & ((1u << lane) - 1u));
                list1[(r << 7) + pos] = h;
            }
        }
        int c1n = __popc(n10) + __popc(n11) + __popc(n12) + __popc(n13);
        __syncthreads();

        // ---- layer 2 ----  i2 = ((h1s@w12 + b_h1h2) + h2s@w22) + b_h2h2
        float d12 = sparse_dot128(w12s, list1 + (r << 7), c1n, h);
        float d22 = sparse_dot128(w22s, list2 + (r << 7), c2, h);
        float i2 = __fadd_rn(__fadd_rn(__fadd_rn(d12, b12a), d22), b12b);
        b2 = __fadd_rn(__fmul_rn(r2, b2), __fmul_rn(omr2, h2sp));
        float B2 = __fadd_rn(B_J0, __fmul_rn(BETA, b2));
        h2m = __fsub_rn(__fadd_rn(__fmul_rn(h2m, a2), __fmul_rn(oma2, i2)),
                        __fmul_rn(B2, h2sp));
        float sp2 = (__fsub_rn(h2m, B2) > 0.0f) ? 1.0f : 0.0f;
        s2c += sp2;

        unsigned bal2 = __ballot_sync(0xffffffffu, sp2 != 0.0f);
        if (lane == 0) m2s[wid] = bal2;
        __syncthreads();

        unsigned n20 = m2s[r * 4 + 0], n21 = m2s[r * 4 + 1];
        unsigned n22 = m2s[r * 4 + 2], n23 = m2s[r * 4 + 3];
        {
            int w4 = wid & 3;
            int off = 0;
            if (w4 > 0) off += __popc(n20);
            if (w4 > 1) off += __popc(n21);
            if (w4 > 2) off += __popc(n22);
            if (sp2 != 0.0f) {
                int pos = off + __popc(bal2 & ((1u << lane) - 1u));
                list2[(r << 7) + pos] = h;
            }
        }
        c2 = __popc(n20) + __popc(n21) + __popc(n22) + __popc(n23);
        __syncthreads();

        // ---- readout (warps 0 and 5; uses NEW h2 spikes) ----
        if (ro) {
            int oo = (lane < OO) ? lane : 0;
            float d2o = sparse_dot20(w2os, list2 + (r << 7), c2, oo);
            float io = __fadd_rn(d2o, bo);
            om = __fadd_rn(__fmul_rn(om, aoo), __fmul_rn(omao, io));
            float v = (lane < OO) ? om : -3.4e38f;
#pragma unroll
            for (int d = 16; d; d >>= 1) v = fmaxf(v, __shfl_xor_sync(0xffffffffu, v, d));
            float e = (lane < OO) ? (float)exp((double)__fsub_rn(om, v)) : 0.f;
            float ssum = e;
#pragma unroll
            for (int d = 16; d; d >>= 1) ssum += __shfl_xor_sync(0xffffffffu, ssum, d);
            if (t > 10) acc = __fadd_rn(acc, __fdiv_rn(e, ssum));
        }

        h1sp = sp1;
        h2sp = sp2;
        c1 = c1n;
        xt = xnext;
    }

    // ---- epilogue (true IEEE division, matching s1 / T) ----
    out[OUT_OFF_S1 + grow * HH + h] = __fdiv_rn(s1c, (float)TT);
    out[OUT_OFF_S2 + grow * HH + h] = __fdiv_rn(s2c, (float)TT);
    if (ro && lane < OO) out[OUT_OFF_ACC + grow * OO + lane] = acc;
}

// ---------------------------------------------------------------------------
// Kernel 3: A_norm = sum|w11*mask0| + sum|w22*mask1|
// ---------------------------------------------------------------------------
__global__ __launch_bounds__(256) void norm_kernel(
    const float* __restrict__ w11, const float* __restrict__ w22,
    const float* __restrict__ mask, float* __restrict__ out)
{
    __shared__ float red[256];
    int tid = threadIdx.x;
    float s = 0.f;
    for (int i = tid; i < 16384; i += 256)
        s += fabsf(__fmul_rn(w11[i], mask[i])) + fabsf(__fmul_rn(w22[i], mask[16384 + i]));
    red[tid] = s;
    __syncthreads();
    for (int d = 128; d > 0; d >>= 1) {
        if (tid < d) red[tid] += red[tid + d];
        __syncthreads();
    }
    if (tid == 0) out[OUT_OFF_NORM] = red[0];
}

// ---------------------------------------------------------------------------
extern "C" void kernel_launch(void* const* d_in, const int* in_sizes, int n_in,
                              void* d_out, int out_size)
{
    const float* x          = (const float*)d_in[0];
    const float* mask       = (const float*)d_in[1];
    const float* w_ih1      = (const float*)d_in[2];
    const float* b_ih1      = (const float*)d_in[3];
    const float* w_h1h1     = (const float*)d_in[4];
    const float* b_h1h1     = (const float*)d_in[5];
    const float* w_h1h2     = (const float*)d_in[6];
    const float* b_h1h2     = (const float*)d_in[7];
    const float* w_h2h2     = (const float*)d_in[8];
    const float* b_h2h2     = (const float*)d_in[9];
    const float* w_h2o      = (const float*)d_in[10];
    const float* b_h2o      = (const float*)d_in[11];
    const float* tau_adp_h1 = (const float*)d_in[12];
    const float* tau_adp_h2 = (const float*)d_in[13];
    const float* tau_m_h1   = (const float*)d_in[14];
    const float* tau_m_h2   = (const float*)d_in[15];
    const float* tau_m_o    = (const float*)d_in[16];
    const float* hid1_mem0  = (const float*)d_in[17];
    const float* hid2_mem0  = (const float*)d_in[18];
    const float* out_mem0   = (const float*)d_in[19];
    float* out = (float*)d_out;

    float* xin = nullptr;
    cudaGetSymbolAddress((void**)&xin, g_xin);

    cudaFuncSetAttribute(scan_kernel, cudaFuncAttributeMaxDynamicSharedMemorySize,
                         SCAN_SMEM_BYTES);

    norm_kernel<<<1, 256>>>(w_h1h1, w_h2h2, mask, out);
    gemm_xin_kernel<<<(BT * TT) / 128, 256>>>(x, w_ih1, b_ih1, xin);
    scan_kernel<<<BT / 2, 256, SCAN_SMEM_BYTES>>>(
        xin, mask, w_h1h1, b_h1h1, w_h1h2, b_h1h2, w_h2h2, b_h2h2,
        w_h2o, b_h2o, tau_adp_h1, tau_adp_h2, tau_m_h1, tau_m_h2, tau_m_o,
        hid1_mem0, hid2_mem0, out_mem0, out);
}